// round 8
// baseline (speedup 1.0000x reference)
#include <cuda_runtime.h>

#define BB     4096
#define TT     2048
#define SDIM   5
#define WPB    4                 // warps per block
#define BPW    2                 // batch elements per warp (one per 16-lane half)
#define CHUNK  16                // delta steps staged per smem refill
#define NCHUNK (TT / CHUNK)

typedef unsigned long long ull;

// ---- packed f32x2 helpers (sm_100+/sm_103a) ----
__device__ __forceinline__ ull pack2(float lo, float hi) {
    ull r; asm("mov.b64 %0, {%1, %2};" : "=l"(r) : "f"(lo), "f"(hi)); return r;
}
__device__ __forceinline__ void unpack2(ull a, float& lo, float& hi) {
    asm("mov.b64 {%0, %1}, %2;" : "=f"(lo), "=f"(hi) : "l"(a));
}
__device__ __forceinline__ ull mul2(ull a, ull b) {
    ull d; asm("mul.rn.f32x2 %0, %1, %2;" : "=l"(d) : "l"(a), "l"(b)); return d;
}
__device__ __forceinline__ ull add2(ull a, ull b) {
    ull d; asm("add.rn.f32x2 %0, %1, %2;" : "=l"(d) : "l"(a), "l"(b)); return d;
}
__device__ __forceinline__ void fma2(ull& d, ull a, ull b) {
    asm("fma.rn.f32x2 %0, %1, %2, %0;" : "+l"(d) : "l"(a), "l"(b));
}

#define SC 2.885390081777926815f   // 2*log2(e): folded into W2/b2 only

// stage-1 tanh: single-instruction HW approx (sm_75+), ~5e-4 abs err (damped by W2)
__device__ __forceinline__ float tanh_hw(float x) {
    float y; asm("tanh.approx.f32 %0, %1;" : "=f"(y) : "f"(x));
    return y;
}
// stage-2 tanh from a PRE-SCALED argument y = 2*log2(e)*x (1e-6 err, on direct path)
__device__ __forceinline__ float tanh_pre(float y) {
    float e, r;
    asm("ex2.approx.f32 %0, %1;" : "=f"(e) : "f"(y));
    asm("rcp.approx.f32 %0, %1;" : "=f"(r) : "f"(e + 1.0f));
    return fmaf(-2.0f, r, 1.0f);
}

__global__ __launch_bounds__(WPB * 32, 4)   // cap 128 regs
void msc_seq_kernel(const float* __restrict__ delta,
                    const float* __restrict__ state0,
                    const float* __restrict__ W1, const float* __restrict__ b1,
                    const float* __restrict__ W2, const float* __restrict__ b2,
                    const float* __restrict__ W3, const float* __restrict__ b3,
                    float* __restrict__ out)
{
    // h1 line per (warp, half); halves 192B apart -> +16 banks, conflict-free
    __shared__ __align__(16) float sh1[WPB][BPW][48];
    // staged delta (float4/step); halves 320B apart -> +16 banks
    __shared__ __align__(16) float shd[WPB][BPW][80];

    const int lane = threadIdx.x & 31;
    const int warp = threadIdx.x >> 5;
    const int h    = lane >> 4;          // which half (batch)
    const int hl   = lane & 15;          // lane within half
    const int b    = (blockIdx.x * WPB + warp) * BPW + h;

    const int j0 = hl, j1 = hl + 16;     // hidden channels owned by this lane

    // ---- weights in registers ----
    float w1a[8], w1b[8];                // UNSCALED (stage-1 uses tanh.approx)
#pragma unroll
    for (int i = 0; i < 8; i++) {
        w1a[i] = W1[i * 32 + j0];
        w1b[i] = W1[i * 32 + j1];
    }
    ull w2p[16], w2q[16];                // prescaled for tanh_pre
#pragma unroll
    for (int p = 0; p < 16; p++) {
        w2p[p] = pack2(W2[(2 * p) * 32 + j0] * SC, W2[(2 * p + 1) * 32 + j0] * SC);
        w2q[p] = pack2(W2[(2 * p) * 32 + j1] * SC, W2[(2 * p + 1) * 32 + j1] * SC);
    }
    float w3a[5], w3b[5];
#pragma unroll
    for (int k = 0; k < 5; k++) {
        w3a[k] = W3[j0 * SDIM + k];
        w3b[k] = W3[j1 * SDIM + k];
    }
    const float b1a = b1[j0], b1c = b1[j1];
    const float b2a = b2[j0] * SC, b2c = b2[j1] * SC;
    const float b30 = b3[0], b31 = b3[1], b32 = b3[2], b33 = b3[3], b34 = b3[4];

    // merge-tree bits (vidx mapping ignores bit0 -> lane pairs share a channel)
    const int b3_ = (hl >> 3) & 1, b2_ = (hl >> 2) & 1, b1_ = (hl >> 1) & 1;

    // every lane carries the full 5-vector state (rebuilt from pair-broadcasts)
    float s0 = state0[b * SDIM + 0];
    float s1 = state0[b * SDIM + 1];
    float s2 = state0[b * SDIM + 2];
    float s3 = state0[b * SDIM + 3];
    float s4 = state0[b * SDIM + 4];

    const float* dptr = delta + (size_t)b * (TT * 3);
    float*       optr = out   + (size_t)b * (TT * SDIM);

    float* line = &sh1[warp][h][0];
    const ulonglong2* hp = (const ulonglong2*)line;

    // prefetch first delta chunk: lane (h,hl) holds step hl of batch b
    float r0 = dptr[hl * 3 + 0];
    float r1 = dptr[hl * 3 + 1];
    float r2 = dptr[hl * 3 + 2];

    for (int c = 0; c < NCHUNK; c++) {
        __syncwarp();                    // prior chunk's delta reads done
        *(float4*)(&shd[warp][h][hl * 4]) = make_float4(r0, r1, r2, 0.f);
        __syncwarp();
        if (c + 1 < NCHUNK) {
            const float* np = dptr + (size_t)(c + 1) * (CHUNK * 3);
            r0 = np[hl * 3 + 0];
            r1 = np[hl * 3 + 1];
            r2 = np[hl * 3 + 2];
        }

#pragma unroll 2
        for (int tl = 0; tl < CHUNK; tl++) {
            const float4 dv = *(const float4*)(&shd[warp][h][tl * 4]);

            // ---- stage 1: delta part first (no dep), then state part ----
            float aa = b1a, ac = b1c;
            aa = fmaf(dv.x, w1a[5], aa); ac = fmaf(dv.x, w1b[5], ac);
            aa = fmaf(dv.y, w1a[6], aa); ac = fmaf(dv.y, w1b[6], ac);
            aa = fmaf(dv.z, w1a[7], aa); ac = fmaf(dv.z, w1b[7], ac);
            aa = fmaf(s0, w1a[0], aa);   ac = fmaf(s0, w1b[0], ac);
            aa = fmaf(s1, w1a[1], aa);   ac = fmaf(s1, w1b[1], ac);
            aa = fmaf(s2, w1a[2], aa);   ac = fmaf(s2, w1b[2], ac);
            aa = fmaf(s3, w1a[3], aa);   ac = fmaf(s3, w1b[3], ac);
            aa = fmaf(s4, w1a[4], aa);   ac = fmaf(s4, w1b[4], ac);
            line[j0] = tanh_hw(aa);      // MUFU.TANH: 1 instr, 16 cyc
            line[j1] = tanh_hw(ac);
            __syncwarp();

            // ---- stage 2: 4 accumulators per channel (depth 4) ----
            ulonglong2 v0 = hp[0], v1 = hp[1], v2 = hp[2], v3 = hp[3];
            ulonglong2 v4 = hp[4], v5 = hp[5], v6 = hp[6], v7 = hp[7];
            ull a0 = mul2(v0.x, w2p[0]);
            ull a1 = mul2(v0.y, w2p[1]);
            ull a2 = mul2(v1.x, w2p[2]);
            ull a3 = mul2(v1.y, w2p[3]);
            ull c0 = mul2(v0.x, w2q[0]);
            ull c1 = mul2(v0.y, w2q[1]);
            ull c2 = mul2(v1.x, w2q[2]);
            ull c3 = mul2(v1.y, w2q[3]);
            fma2(a0, v2.x, w2p[4]);  fma2(a1, v2.y, w2p[5]);
            fma2(a2, v3.x, w2p[6]);  fma2(a3, v3.y, w2p[7]);
            fma2(c0, v2.x, w2q[4]);  fma2(c1, v2.y, w2q[5]);
            fma2(c2, v3.x, w2q[6]);  fma2(c3, v3.y, w2q[7]);
            fma2(a0, v4.x, w2p[8]);  fma2(a1, v4.y, w2p[9]);
            fma2(a2, v5.x, w2p[10]); fma2(a3, v5.y, w2p[11]);
            fma2(c0, v4.x, w2q[8]);  fma2(c1, v4.y, w2q[9]);
            fma2(c2, v5.x, w2q[10]); fma2(c3, v5.y, w2q[11]);
            fma2(a0, v6.x, w2p[12]); fma2(a1, v6.y, w2p[13]);
            fma2(a2, v7.x, w2p[14]); fma2(a3, v7.y, w2p[15]);
            fma2(c0, v6.x, w2q[12]); fma2(c1, v6.y, w2q[13]);
            fma2(c2, v7.x, w2q[14]); fma2(c3, v7.y, w2q[15]);
            float lo, hi;
            unpack2(add2(add2(a0, a1), add2(a2, a3)), lo, hi);
            const float h2a = tanh_pre(lo + hi + b2a);
            unpack2(add2(add2(c0, c1), add2(c2, c3)), lo, hi);
            const float h2c = tanh_pre(lo + hi + b2c);

            // ---- stage 3: products, 3-round tree (parity partials) ----
            const float p0 = fmaf(h2c, w3b[0], h2a * w3a[0]);
            const float p1 = fmaf(h2c, w3b[1], h2a * w3a[1]);
            const float p2 = fmaf(h2c, w3b[2], h2a * w3a[2]);
            const float p3 = fmaf(h2c, w3b[3], h2a * w3a[3]);
            float       p4 = fmaf(h2c, w3b[4], h2a * w3a[4]);

            // r1 (xor 8): (p0,p1)->A, (p2,p3)->B, p4 butterfly
            float A  = b3_ ? p1 : p0;
            float Au = b3_ ? p0 : p1;
            A += __shfl_xor_sync(0xffffffffu, Au, 8);
            float Bt = b3_ ? p3 : p2;
            float Bu = b3_ ? p2 : p3;
            Bt += __shfl_xor_sync(0xffffffffu, Bu, 8);
            p4 += __shfl_xor_sync(0xffffffffu, p4, 8);
            // r2 (xor 4): (A,B)->C, p4 butterfly
            float Ct = b2_ ? Bt : A;
            float Cu = b2_ ? A : Bt;
            Ct += __shfl_xor_sync(0xffffffffu, Cu, 4);
            p4 += __shfl_xor_sync(0xffffffffu, p4, 4);
            // r3 (xor 2): (C,p4)->D  — STOP here (parity partial per lane)
            float D  = b1_ ? p4 : Ct;
            float Du = b1_ ? Ct : p4;
            D += __shfl_xor_sync(0xffffffffu, Du, 2);

            // ---- pair-broadcast: even/odd parity halves of each channel ----
            // pairs: {0,1}->ch0 {8,9}->ch1 {4,5}->ch2 {12,13}->ch3 {2,3}->ch4
            const float e0 = __shfl_sync(0xffffffffu, D, 0, 16);
            const float o0 = __shfl_sync(0xffffffffu, D, 1, 16);
            const float e1 = __shfl_sync(0xffffffffu, D, 8, 16);
            const float o1 = __shfl_sync(0xffffffffu, D, 9, 16);
            const float e2 = __shfl_sync(0xffffffffu, D, 4, 16);
            const float o2 = __shfl_sync(0xffffffffu, D, 5, 16);
            const float e3 = __shfl_sync(0xffffffffu, D, 12, 16);
            const float o3 = __shfl_sync(0xffffffffu, D, 13, 16);
            const float e4 = __shfl_sync(0xffffffffu, D, 2, 16);
            const float o4 = __shfl_sync(0xffffffffu, D, 3, 16);

            s0 += (e0 + o0) + b30;
            s1 += (e1 + o1) + b31;
            s2 += (e2 + o2) + b32;
            s3 += (e3 + o3) + b33;
            s4 += (e4 + o4) + b34;

            // ---- store: lanes hl<5 write channel hl ----
            float v = s0;
            v = (hl == 1) ? s1 : v;
            v = (hl == 2) ? s2 : v;
            v = (hl == 3) ? s3 : v;
            v = (hl == 4) ? s4 : v;
            if (hl < SDIM) optr[hl] = v;
            optr += SDIM;
        }
    }
}

extern "C" void kernel_launch(void* const* d_in, const int* in_sizes, int n_in,
                              void* d_out, int out_size)
{
    const float* delta  = (const float*)d_in[0];
    const float* state0 = (const float*)d_in[1];
    const float* W1     = (const float*)d_in[2];
    const float* b1     = (const float*)d_in[3];
    const float* W2     = (const float*)d_in[4];
    const float* b2     = (const float*)d_in[5];
    const float* W3     = (const float*)d_in[6];
    const float* b3     = (const float*)d_in[7];
    float* out = (float*)d_out;

    dim3 grid(BB / (WPB * BPW));     // 512 blocks: 2048 warps, 2 batches each
    dim3 block(WPB * 32);
    msc_seq_kernel<<<grid, block>>>(delta, state0, W1, b1, W2, b2, W3, b3, out);
}

// round 9
// speedup vs baseline: 1.1301x; 1.1301x over previous
#include <cuda_runtime.h>

#define BB     4096
#define TT     2048
#define SDIM   5
#define WPB    4                 // warps per block
#define BPW    2                 // batch elements per warp (one per 16-lane half)
#define CHUNK  16                // delta steps staged per smem refill
#define NCHUNK (TT / CHUNK)

typedef unsigned long long ull;

// ---- packed f32x2 helpers (sm_100+/sm_103a) ----
__device__ __forceinline__ ull pack2(float lo, float hi) {
    ull r; asm("mov.b64 %0, {%1, %2};" : "=l"(r) : "f"(lo), "f"(hi)); return r;
}
__device__ __forceinline__ void unpack2(ull a, float& lo, float& hi) {
    asm("mov.b64 {%0, %1}, %2;" : "=f"(lo), "=f"(hi) : "l"(a));
}
__device__ __forceinline__ ull mul2(ull a, ull b) {
    ull d; asm("mul.rn.f32x2 %0, %1, %2;" : "=l"(d) : "l"(a), "l"(b)); return d;
}
__device__ __forceinline__ ull add2(ull a, ull b) {
    ull d; asm("add.rn.f32x2 %0, %1, %2;" : "=l"(d) : "l"(a), "l"(b)); return d;
}
__device__ __forceinline__ void fma2(ull& d, ull a, ull b) {
    asm("fma.rn.f32x2 %0, %1, %2, %0;" : "+l"(d) : "l"(a), "l"(b));
}

#define SC 2.885390081777926815f   // 2*log2(e): folded into W2/b2 only

// stage-1 tanh: single-instruction HW approx (validated: rel_err impact ~2e-5)
__device__ __forceinline__ float tanh_hw(float x) {
    float y; asm("tanh.approx.f32 %0, %1;" : "=f"(y) : "f"(x));
    return y;
}
// stage-2 tanh from PRE-SCALED argument y = 2*log2(e)*x (1e-6 err, direct path)
__device__ __forceinline__ float tanh_pre(float y) {
    float e, r;
    asm("ex2.approx.f32 %0, %1;" : "=f"(e) : "f"(y));
    asm("rcp.approx.f32 %0, %1;" : "=f"(r) : "f"(e + 1.0f));
    return fmaf(-2.0f, r, 1.0f);
}

__global__ __launch_bounds__(WPB * 32, 4)   // cap 128 regs
void msc_seq_kernel(const float* __restrict__ delta,
                    const float* __restrict__ state0,
                    const float* __restrict__ W1, const float* __restrict__ b1,
                    const float* __restrict__ W2, const float* __restrict__ b2,
                    const float* __restrict__ W3, const float* __restrict__ b3,
                    float* __restrict__ out)
{
    // h1 line per (warp, half); halves 192B apart -> +16 banks, conflict-free
    __shared__ __align__(16) float sh1[WPB][BPW][48];
    // staged delta (float4/step); halves 320B apart -> +16 banks
    __shared__ __align__(16) float shd[WPB][BPW][80];

    const int lane = threadIdx.x & 31;
    const int warp = threadIdx.x >> 5;
    const int h    = lane >> 4;          // which half (batch)
    const int hl   = lane & 15;          // lane within half
    const int b    = (blockIdx.x * WPB + warp) * BPW + h;

    const int j0 = 2 * hl, j1 = 2 * hl + 1;   // ADJACENT owned channels -> STS.64

    // ---- weights in registers ----
    float w1a[8], w1b[8];                // UNSCALED (stage-1 uses tanh.approx)
#pragma unroll
    for (int i = 0; i < 8; i++) {
        w1a[i] = W1[i * 32 + j0];
        w1b[i] = W1[i * 32 + j1];
    }
    ull w2p[16], w2q[16];                // prescaled for tanh_pre
#pragma unroll
    for (int p = 0; p < 16; p++) {
        w2p[p] = pack2(W2[(2 * p) * 32 + j0] * SC, W2[(2 * p + 1) * 32 + j0] * SC);
        w2q[p] = pack2(W2[(2 * p) * 32 + j1] * SC, W2[(2 * p + 1) * 32 + j1] * SC);
    }
    float w3a[5], w3b[5];
#pragma unroll
    for (int k = 0; k < 5; k++) {
        w3a[k] = W3[j0 * SDIM + k];      // UNscaled (feeds residual state)
        w3b[k] = W3[j1 * SDIM + k];
    }
    const float b1a = b1[j0], b1c = b1[j1];
    const float b2a = b2[j0] * SC, b2c = b2[j1] * SC;

    // ---- slot mapping (16-lane merge tree, as in R5) ----
    const int b3_ = (hl >> 3) & 1, b2_ = (hl >> 2) & 1, b1_ = (hl >> 1) & 1;
    const int vidx = b1_ ? 4 : (b2_ ? (b3_ ? 3 : 2) : (b3_ ? 1 : 0));
    const bool wr  = (hl == 0) | (hl == 8) | (hl == 4) | (hl == 12) | (hl == 2);
    const float b3v = b3[vidx];

    float stv = state0[b * SDIM + vidx]; // lane carries its slot's state channel

    const float* dptr = delta + (size_t)b * (TT * 3);
    float*       optr = out   + (size_t)b * (TT * SDIM) + vidx;

    float* line = &sh1[warp][h][0];
    const ulonglong2* hp = (const ulonglong2*)line;

    // prefetch first delta chunk: lane (h,hl) holds step hl of batch b
    float r0 = dptr[hl * 3 + 0];
    float r1 = dptr[hl * 3 + 1];
    float r2 = dptr[hl * 3 + 2];

    for (int c = 0; c < NCHUNK; c++) {
        __syncwarp();                    // prior chunk's delta reads done
        *(float4*)(&shd[warp][h][hl * 4]) = make_float4(r0, r1, r2, 0.f);
        __syncwarp();
        if (c + 1 < NCHUNK) {
            const float* np = dptr + (size_t)(c + 1) * (CHUNK * 3);
            r0 = np[hl * 3 + 0];
            r1 = np[hl * 3 + 1];
            r2 = np[hl * 3 + 2];
        }

#pragma unroll 2
        for (int tl = 0; tl < CHUNK; tl++) {
            const float4 dv = *(const float4*)(&shd[warp][h][tl * 4]);

            // ---- broadcast state channels within the half (width=16 shfl) ----
            const float s0b = __shfl_sync(0xffffffffu, stv, 0, 16);
            const float s1b = __shfl_sync(0xffffffffu, stv, 8, 16);
            const float s2b = __shfl_sync(0xffffffffu, stv, 4, 16);
            const float s3b = __shfl_sync(0xffffffffu, stv, 12, 16);
            const float s4b = __shfl_sync(0xffffffffu, stv, 2, 16);

            // ---- stage 1: h1 for both owned channels ----
            float aa = b1a, ac = b1c;
            aa = fmaf(dv.x, w1a[5], aa); ac = fmaf(dv.x, w1b[5], ac);
            aa = fmaf(dv.y, w1a[6], aa); ac = fmaf(dv.y, w1b[6], ac);
            aa = fmaf(dv.z, w1a[7], aa); ac = fmaf(dv.z, w1b[7], ac);
            aa = fmaf(s0b, w1a[0], aa);  ac = fmaf(s0b, w1b[0], ac);
            aa = fmaf(s1b, w1a[1], aa);  ac = fmaf(s1b, w1b[1], ac);
            aa = fmaf(s2b, w1a[2], aa);  ac = fmaf(s2b, w1b[2], ac);
            aa = fmaf(s3b, w1a[3], aa);  ac = fmaf(s3b, w1b[3], ac);
            aa = fmaf(s4b, w1a[4], aa);  ac = fmaf(s4b, w1b[4], ac);
            const float h1a = tanh_hw(aa);   // MUFU.TANH: 1 instr
            const float h1c = tanh_hw(ac);

            // adjacent channels -> single STS.64
            *(float2*)(&line[j0]) = make_float2(h1a, h1c);
            __syncwarp();

            // ---- stage 2: 4 accumulators per channel (depth 4, packed f32x2) ----
            ulonglong2 v0 = hp[0], v1 = hp[1], v2 = hp[2], v3 = hp[3];
            ulonglong2 v4 = hp[4], v5 = hp[5], v6 = hp[6], v7 = hp[7];
            ull a0 = mul2(v0.x, w2p[0]);
            ull a1 = mul2(v0.y, w2p[1]);
            ull a2 = mul2(v1.x, w2p[2]);
            ull a3 = mul2(v1.y, w2p[3]);
            ull c0 = mul2(v0.x, w2q[0]);
            ull c1 = mul2(v0.y, w2q[1]);
            ull c2 = mul2(v1.x, w2q[2]);
            ull c3 = mul2(v1.y, w2q[3]);
            fma2(a0, v2.x, w2p[4]);  fma2(a1, v2.y, w2p[5]);
            fma2(a2, v3.x, w2p[6]);  fma2(a3, v3.y, w2p[7]);
            fma2(c0, v2.x, w2q[4]);  fma2(c1, v2.y, w2q[5]);
            fma2(c2, v3.x, w2q[6]);  fma2(c3, v3.y, w2q[7]);
            fma2(a0, v4.x, w2p[8]);  fma2(a1, v4.y, w2p[9]);
            fma2(a2, v5.x, w2p[10]); fma2(a3, v5.y, w2p[11]);
            fma2(c0, v4.x, w2q[8]);  fma2(c1, v4.y, w2q[9]);
            fma2(c2, v5.x, w2q[10]); fma2(c3, v5.y, w2q[11]);
            fma2(a0, v6.x, w2p[12]); fma2(a1, v6.y, w2p[13]);
            fma2(a2, v7.x, w2p[14]); fma2(a3, v7.y, w2p[15]);
            fma2(c0, v6.x, w2q[12]); fma2(c1, v6.y, w2q[13]);
            fma2(c2, v7.x, w2q[14]); fma2(c3, v7.y, w2q[15]);
            float lo, hi;
            unpack2(add2(add2(a0, a1), add2(a2, a3)), lo, hi);
            const float h2a = tanh_pre(lo + hi + b2a);
            unpack2(add2(add2(c0, c1), add2(c2, c3)), lo, hi);
            const float h2c = tanh_pre(lo + hi + b2c);

            // ---- stage 3: products, then 16-lane slot-merge tree (7 shfl) ----
            const float p0 = fmaf(h2c, w3b[0], h2a * w3a[0]);
            const float p1 = fmaf(h2c, w3b[1], h2a * w3a[1]);
            const float p2 = fmaf(h2c, w3b[2], h2a * w3a[2]);
            const float p3 = fmaf(h2c, w3b[3], h2a * w3a[3]);
            float       p4 = fmaf(h2c, w3b[4], h2a * w3a[4]);

            // r1 (xor 8): (p0,p1)->A, (p2,p3)->B, p4 butterfly
            float A  = b3_ ? p1 : p0;
            float Au = b3_ ? p0 : p1;
            A += __shfl_xor_sync(0xffffffffu, Au, 8);
            float Bt = b3_ ? p3 : p2;
            float Bu = b3_ ? p2 : p3;
            Bt += __shfl_xor_sync(0xffffffffu, Bu, 8);
            p4 += __shfl_xor_sync(0xffffffffu, p4, 8);
            // r2 (xor 4): (A,B)->C, p4 butterfly
            float Ct = b2_ ? Bt : A;
            float Cu = b2_ ? A : Bt;
            Ct += __shfl_xor_sync(0xffffffffu, Cu, 4);
            p4 += __shfl_xor_sync(0xffffffffu, p4, 4);
            // r3 (xor 2): (C,p4)->D
            float D  = b1_ ? p4 : Ct;
            float Du = b1_ ? Ct : p4;
            D += __shfl_xor_sync(0xffffffffu, Du, 2);
            // r4 (xor 1): butterfly
            D += __shfl_xor_sync(0xffffffffu, D, 1);

            stv += D + b3v;              // every lane updates its slot channel

            if (wr) *optr = stv;         // lanes {0,8,4,12,2} -> channels {0..4}
            optr += SDIM;
        }
    }
}

extern "C" void kernel_launch(void* const* d_in, const int* in_sizes, int n_in,
                              void* d_out, int out_size)
{
    const float* delta  = (const float*)d_in[0];
    const float* state0 = (const float*)d_in[1];
    const float* W1     = (const float*)d_in[2];
    const float* b1     = (const float*)d_in[3];
    const float* W2     = (const float*)d_in[4];
    const float* b2     = (const float*)d_in[5];
    const float* W3     = (const float*)d_in[6];
    const float* b3     = (const float*)d_in[7];
    float* out = (float*)d_out;

    dim3 grid(BB / (WPB * BPW));     // 512 blocks: 2048 warps, 2 batches each
    dim3 block(WPB * 32);
    msc_seq_kernel<<<grid, block>>>(delta, state0, W1, b1, W2, b2, W3, b3, out);
}

// round 10
// speedup vs baseline: 1.1768x; 1.0414x over previous
#include <cuda_runtime.h>

#define BB     4096
#define TT     2048
#define SDIM   5
#define CHUNK  16                // delta steps staged per smem refill
#define NCHUNK (TT / CHUNK)

typedef unsigned long long ull;

// ---- packed f32x2 helpers (sm_100+/sm_103a) ----
__device__ __forceinline__ ull pack2(float lo, float hi) {
    ull r; asm("mov.b64 %0, {%1, %2};" : "=l"(r) : "f"(lo), "f"(hi)); return r;
}
__device__ __forceinline__ void unpack2(ull a, float& lo, float& hi) {
    asm("mov.b64 {%0, %1}, %2;" : "=f"(lo), "=f"(hi) : "l"(a));
}
__device__ __forceinline__ ull mul2(ull a, ull b) {
    ull d; asm("mul.rn.f32x2 %0, %1, %2;" : "=l"(d) : "l"(a), "l"(b)); return d;
}
__device__ __forceinline__ ull add2(ull a, ull b) {
    ull d; asm("add.rn.f32x2 %0, %1, %2;" : "=l"(d) : "l"(a), "l"(b)); return d;
}
__device__ __forceinline__ void fma2(ull& d, ull a, ull b) {
    asm("fma.rn.f32x2 %0, %1, %2, %0;" : "+l"(d) : "l"(a), "l"(b));
}

#define SC 2.885390081777926815f   // 2*log2(e): folded into W2/b2 only

// stage-1 tanh: single-instruction HW approx (validated: rel_err impact ~2e-5)
__device__ __forceinline__ float tanh_hw(float x) {
    float y; asm("tanh.approx.f32 %0, %1;" : "=f"(y) : "f"(x));
    return y;
}
// stage-2 tanh from PRE-SCALED argument y = 2*log2(e)*x (1e-6 err, direct path)
__device__ __forceinline__ float tanh_pre(float y) {
    float e, r;
    asm("ex2.approx.f32 %0, %1;" : "=f"(e) : "f"(y));
    asm("rcp.approx.f32 %0, %1;" : "=f"(r) : "f"(e + 1.0f));
    return fmaf(-2.0f, r, 1.0f);
}

__global__ __launch_bounds__(32)   // 1 warp per block; regs effectively uncapped
void msc_seq_kernel(const float* __restrict__ delta,
                    const float* __restrict__ state0,
                    const float* __restrict__ W1, const float* __restrict__ b1,
                    const float* __restrict__ W2, const float* __restrict__ b2,
                    const float* __restrict__ W3, const float* __restrict__ b3,
                    float* __restrict__ out)
{
    // h1 lines: [buf][seq][half][48]; halves 192B apart -> +16 banks, conflict-free
    __shared__ __align__(16) float sh1[2][2][2][48];
    // staged delta: [seq][half][80] (float4/step); halves 320B apart -> +16 banks
    __shared__ __align__(16) float shd[2][2][80];

    const int lane = threadIdx.x;        // 32-thread block = one warp
    const int h    = lane >> 4;          // which half (batch group)
    const int hl   = lane & 15;          // lane within half
    const int bA   = blockIdx.x * 4 + h * 2;   // two interleaved batches per half
    const int bB   = bA + 1;

    const int j0 = 2 * hl, j1 = 2 * hl + 1;    // ADJACENT owned channels -> STS.64

    // ---- weights in registers (SHARED across both interleaved sequences) ----
    float w1a[8], w1b[8];                // UNSCALED (stage-1 uses tanh.approx)
#pragma unroll
    for (int i = 0; i < 8; i++) {
        w1a[i] = W1[i * 32 + j0];
        w1b[i] = W1[i * 32 + j1];
    }
    ull w2p[16], w2q[16];                // prescaled for tanh_pre
#pragma unroll
    for (int p = 0; p < 16; p++) {
        w2p[p] = pack2(W2[(2 * p) * 32 + j0] * SC, W2[(2 * p + 1) * 32 + j0] * SC);
        w2q[p] = pack2(W2[(2 * p) * 32 + j1] * SC, W2[(2 * p + 1) * 32 + j1] * SC);
    }
    float w3a[5], w3b[5];
#pragma unroll
    for (int k = 0; k < 5; k++) {
        w3a[k] = W3[j0 * SDIM + k];      // UNscaled (feeds residual state)
        w3b[k] = W3[j1 * SDIM + k];
    }
    const float b1a = b1[j0], b1c = b1[j1];
    const float b2a = b2[j0] * SC, b2c = b2[j1] * SC;

    // ---- slot mapping (16-lane merge tree) ----
    const int b3_ = (hl >> 3) & 1, b2_ = (hl >> 2) & 1, b1_ = (hl >> 1) & 1;
    const int vidx = b1_ ? 4 : (b2_ ? (b3_ ? 3 : 2) : (b3_ ? 1 : 0));
    const bool wr  = (hl == 0) | (hl == 8) | (hl == 4) | (hl == 12) | (hl == 2);
    const float b3v = b3[vidx];

    float stvA = state0[bA * SDIM + vidx];
    float stvB = state0[bB * SDIM + vidx];

    const float* dApt = delta + (size_t)bA * (TT * 3);
    const float* dBpt = delta + (size_t)bB * (TT * 3);
    float* oA = out + (size_t)bA * (TT * SDIM) + vidx;
    float* oB = out + (size_t)bB * (TT * SDIM) + vidx;

    // prefetch first delta chunk for both sequences
    float rA0 = dApt[hl * 3 + 0], rA1 = dApt[hl * 3 + 1], rA2 = dApt[hl * 3 + 2];
    float rB0 = dBpt[hl * 3 + 0], rB1 = dBpt[hl * 3 + 1], rB2 = dBpt[hl * 3 + 2];

    // ---- per-sequence step phases ----
    auto phase1 = [&](float stv, const float4 dv, float* line) {
        const float s0b = __shfl_sync(0xffffffffu, stv, 0, 16);
        const float s1b = __shfl_sync(0xffffffffu, stv, 8, 16);
        const float s2b = __shfl_sync(0xffffffffu, stv, 4, 16);
        const float s3b = __shfl_sync(0xffffffffu, stv, 12, 16);
        const float s4b = __shfl_sync(0xffffffffu, stv, 2, 16);

        float aa = b1a, ac = b1c;
        aa = fmaf(dv.x, w1a[5], aa); ac = fmaf(dv.x, w1b[5], ac);
        aa = fmaf(dv.y, w1a[6], aa); ac = fmaf(dv.y, w1b[6], ac);
        aa = fmaf(dv.z, w1a[7], aa); ac = fmaf(dv.z, w1b[7], ac);
        aa = fmaf(s0b, w1a[0], aa);  ac = fmaf(s0b, w1b[0], ac);
        aa = fmaf(s1b, w1a[1], aa);  ac = fmaf(s1b, w1b[1], ac);
        aa = fmaf(s2b, w1a[2], aa);  ac = fmaf(s2b, w1b[2], ac);
        aa = fmaf(s3b, w1a[3], aa);  ac = fmaf(s3b, w1b[3], ac);
        aa = fmaf(s4b, w1a[4], aa);  ac = fmaf(s4b, w1b[4], ac);
        // adjacent channels -> single STS.64
        *(float2*)(&line[j0]) = make_float2(tanh_hw(aa), tanh_hw(ac));
    };

    auto phase23 = [&](float& stv, const float* line, float* op) {
        const ulonglong2* hp = (const ulonglong2*)line;
        ulonglong2 v0 = hp[0], v1 = hp[1], v2 = hp[2], v3 = hp[3];
        ulonglong2 v4 = hp[4], v5 = hp[5], v6 = hp[6], v7 = hp[7];
        ull a0 = mul2(v0.x, w2p[0]);
        ull a1 = mul2(v0.y, w2p[1]);
        ull a2 = mul2(v1.x, w2p[2]);
        ull a3 = mul2(v1.y, w2p[3]);
        ull c0 = mul2(v0.x, w2q[0]);
        ull c1 = mul2(v0.y, w2q[1]);
        ull c2 = mul2(v1.x, w2q[2]);
        ull c3 = mul2(v1.y, w2q[3]);
        fma2(a0, v2.x, w2p[4]);  fma2(a1, v2.y, w2p[5]);
        fma2(a2, v3.x, w2p[6]);  fma2(a3, v3.y, w2p[7]);
        fma2(c0, v2.x, w2q[4]);  fma2(c1, v2.y, w2q[5]);
        fma2(c2, v3.x, w2q[6]);  fma2(c3, v3.y, w2q[7]);
        fma2(a0, v4.x, w2p[8]);  fma2(a1, v4.y, w2p[9]);
        fma2(a2, v5.x, w2p[10]); fma2(a3, v5.y, w2p[11]);
        fma2(c0, v4.x, w2q[8]);  fma2(c1, v4.y, w2q[9]);
        fma2(c2, v5.x, w2q[10]); fma2(c3, v5.y, w2q[11]);
        fma2(a0, v6.x, w2p[12]); fma2(a1, v6.y, w2p[13]);
        fma2(a2, v7.x, w2p[14]); fma2(a3, v7.y, w2p[15]);
        fma2(c0, v6.x, w2q[12]); fma2(c1, v6.y, w2q[13]);
        fma2(c2, v7.x, w2q[14]); fma2(c3, v7.y, w2q[15]);
        float lo, hi;
        unpack2(add2(add2(a0, a1), add2(a2, a3)), lo, hi);
        const float h2a = tanh_pre(lo + hi + b2a);
        unpack2(add2(add2(c0, c1), add2(c2, c3)), lo, hi);
        const float h2c = tanh_pre(lo + hi + b2c);

        // products for the 5 output channels
        const float p0 = fmaf(h2c, w3b[0], h2a * w3a[0]);
        const float p1 = fmaf(h2c, w3b[1], h2a * w3a[1]);
        const float p2 = fmaf(h2c, w3b[2], h2a * w3a[2]);
        const float p3 = fmaf(h2c, w3b[3], h2a * w3a[3]);
        float       p4 = fmaf(h2c, w3b[4], h2a * w3a[4]);

        // 16-lane slot-merge tree (7 shfl)
        float A  = b3_ ? p1 : p0;
        float Au = b3_ ? p0 : p1;
        A += __shfl_xor_sync(0xffffffffu, Au, 8);
        float Bt = b3_ ? p3 : p2;
        float Bu = b3_ ? p2 : p3;
        Bt += __shfl_xor_sync(0xffffffffu, Bu, 8);
        p4 += __shfl_xor_sync(0xffffffffu, p4, 8);
        float Ct = b2_ ? Bt : A;
        float Cu = b2_ ? A : Bt;
        Ct += __shfl_xor_sync(0xffffffffu, Cu, 4);
        p4 += __shfl_xor_sync(0xffffffffu, p4, 4);
        float D  = b1_ ? p4 : Ct;
        float Du = b1_ ? Ct : p4;
        D += __shfl_xor_sync(0xffffffffu, Du, 2);
        D += __shfl_xor_sync(0xffffffffu, D, 1);

        stv += D + b3v;
        if (wr) *op = stv;               // lanes {0,8,4,12,2} -> channels {0..4}
    };

    for (int c = 0; c < NCHUNK; c++) {
        __syncwarp();                    // prior chunk's delta reads done
        *(float4*)(&shd[0][h][hl * 4]) = make_float4(rA0, rA1, rA2, 0.f);
        *(float4*)(&shd[1][h][hl * 4]) = make_float4(rB0, rB1, rB2, 0.f);
        __syncwarp();
        if (c + 1 < NCHUNK) {
            const float* nA = dApt + (size_t)(c + 1) * (CHUNK * 3);
            const float* nB = dBpt + (size_t)(c + 1) * (CHUNK * 3);
            rA0 = nA[hl * 3 + 0]; rA1 = nA[hl * 3 + 1]; rA2 = nA[hl * 3 + 2];
            rB0 = nB[hl * 3 + 0]; rB1 = nB[hl * 3 + 1]; rB2 = nB[hl * 3 + 2];
        }

#pragma unroll 2
        for (int tl = 0; tl < CHUNK; tl++) {
            const int buf = tl & 1;
            const float4 dvA = *(const float4*)(&shd[0][h][tl * 4]);
            const float4 dvB = *(const float4*)(&shd[1][h][tl * 4]);

            phase1(stvA, dvA, &sh1[buf][0][h][0]);
            phase1(stvB, dvB, &sh1[buf][1][h][0]);
            __syncwarp();                // one sync serves both sequences

            phase23(stvA, &sh1[buf][0][h][0], oA);
            phase23(stvB, &sh1[buf][1][h][0], oB);
            oA += SDIM;
            oB += SDIM;
        }
    }
}

extern "C" void kernel_launch(void* const* d_in, const int* in_sizes, int n_in,
                              void* d_out, int out_size)
{
    const float* delta  = (const float*)d_in[0];
    const float* state0 = (const float*)d_in[1];
    const float* W1     = (const float*)d_in[2];
    const float* b1     = (const float*)d_in[3];
    const float* W2     = (const float*)d_in[4];
    const float* b2     = (const float*)d_in[5];
    const float* W3     = (const float*)d_in[6];
    const float* b3     = (const float*)d_in[7];
    float* out = (float*)d_out;

    dim3 grid(BB / 4);       // 1024 one-warp blocks, 4 batches each -> near-perfect balance
    dim3 block(32);
    msc_seq_kernel<<<grid, block>>>(delta, state0, W1, b1, W2, b2, W3, b3, out);
}